// round 6
// baseline (speedup 1.0000x reference)
#include <cuda_runtime.h>

#define NUM_NODES 1000000
#define NUM_EDGES 16000000
#define F  6
#define FP 8           // padded row: 32B = one L2 sector
#define SCAN_BLK 1024
#define NBLK ((NUM_NODES + SCAN_BLK - 1) / SCAN_BLK)   // 977

// Scratch (device globals; no allocation anywhere).
__device__ __align__(128) float g_x8 [NUM_NODES * FP];   // padded x
__device__ __align__(128) float g_h8 [NUM_NODES * FP];   // padded layer-1 output
__device__ __align__(128) int   g_sorted[NUM_EDGES];     // src ids grouped by dst
__device__ __align__(128) int   g_cnt   [NUM_NODES];     // in-degree
__device__ __align__(128) int   g_rowst [NUM_NODES];     // exclusive scan of cnt
__device__ __align__(128) int   g_cursor[NUM_NODES];     // mutable copy for reorder
__device__ __align__(128) int   g_bsum  [NBLK];          // scan block sums
__device__ int g_idx_is32;

// ---------------------------------------------------------------------------
// detect edge-index dtype (int32 vs int64), runs every launch.
// ---------------------------------------------------------------------------
__global__ void detect_kernel(const long long* __restrict__ ei) {
    __shared__ int bad;
    if (threadIdx.x == 0) bad = 0;
    __syncthreads();
    #pragma unroll
    for (int r = 0; r < 16; r++) {
        long long v = ei[threadIdx.x + r * 256];
        if ((unsigned long long)v >= (unsigned long long)NUM_NODES) bad = 1;
    }
    __syncthreads();
    if (threadIdx.x == 0) g_idx_is32 = bad;
}

// ---------------------------------------------------------------------------
// prep: pad x into g_x8 and zero the degree counters.
// ---------------------------------------------------------------------------
__global__ void prep_kernel(const float* __restrict__ x) {
    int i = blockIdx.x * blockDim.x + threadIdx.x;
    if (i >= NUM_NODES) return;
    const float* xr = x + (size_t)i * F;
    float4* px = reinterpret_cast<float4*>(g_x8 + (size_t)i * FP);
    px[0] = make_float4(xr[0], xr[1], xr[2], xr[3]);
    px[1] = make_float4(xr[4], xr[5], 0.f, 0.f);
    g_cnt[i] = 0;
}

// ---------------------------------------------------------------------------
// histogram of destination ids. 4 edges/thread.
// ---------------------------------------------------------------------------
__global__ void hist_kernel(const void* __restrict__ ei) {
    int i = blockIdx.x * blockDim.x + threadIdx.x;   // edge-quad
    if (i >= NUM_EDGES / 4) return;
    unsigned d[4];
    if (g_idx_is32) {
        const int* dst = (const int*)ei + NUM_EDGES;
        int4 dv = __ldcs(reinterpret_cast<const int4*>(dst) + i);
        d[0] = dv.x; d[1] = dv.y; d[2] = dv.z; d[3] = dv.w;
    } else {
        const long long* dst = (const long long*)ei + NUM_EDGES;
        longlong2 d0 = __ldcs(reinterpret_cast<const longlong2*>(dst) + 2 * i);
        longlong2 d1 = __ldcs(reinterpret_cast<const longlong2*>(dst) + 2 * i + 1);
        d[0] = (unsigned)d0.x; d[1] = (unsigned)d0.y;
        d[2] = (unsigned)d1.x; d[3] = (unsigned)d1.y;
    }
    #pragma unroll
    for (int e = 0; e < 4; e++)
        if (d[e] < NUM_NODES) atomicAdd(&g_cnt[d[e]], 1);
}

// ---------------------------------------------------------------------------
// 3-kernel exclusive scan of g_cnt -> g_rowst (+ g_cursor copy).
// ---------------------------------------------------------------------------
__global__ void scan1_kernel() {
    __shared__ int s[SCAN_BLK];
    int t = threadIdx.x;
    int gid = blockIdx.x * SCAN_BLK + t;
    int v = (gid < NUM_NODES) ? g_cnt[gid] : 0;
    s[t] = v;
    for (int off = 1; off < SCAN_BLK; off <<= 1) {
        __syncthreads();
        int add = (t >= off) ? s[t - off] : 0;
        __syncthreads();
        s[t] += add;
    }
    __syncthreads();
    if (gid < NUM_NODES) g_rowst[gid] = s[t] - v;       // exclusive
    if (t == SCAN_BLK - 1) g_bsum[blockIdx.x] = s[t];   // block total
}

__global__ void scan2_kernel() {
    __shared__ int s[SCAN_BLK];
    int t = threadIdx.x;
    int v = (t < NBLK) ? g_bsum[t] : 0;
    s[t] = v;
    for (int off = 1; off < SCAN_BLK; off <<= 1) {
        __syncthreads();
        int add = (t >= off) ? s[t - off] : 0;
        __syncthreads();
        s[t] += add;
    }
    __syncthreads();
    if (t < NBLK) g_bsum[t] = s[t] - v;                 // exclusive
}

__global__ void scan3_kernel() {
    int gid = blockIdx.x * SCAN_BLK + threadIdx.x;
    if (gid >= NUM_NODES) return;
    int r = g_rowst[gid] + g_bsum[blockIdx.x];
    g_rowst[gid]  = r;
    g_cursor[gid] = r;
}

// ---------------------------------------------------------------------------
// reorder: group src ids by destination. 4 edges/thread.
// ---------------------------------------------------------------------------
__global__ void reorder_kernel(const void* __restrict__ ei) {
    int i = blockIdx.x * blockDim.x + threadIdx.x;
    if (i >= NUM_EDGES / 4) return;
    unsigned s[4], d[4];
    if (g_idx_is32) {
        const int* src = (const int*)ei;
        const int* dst = src + NUM_EDGES;
        int4 sv = __ldcs(reinterpret_cast<const int4*>(src) + i);
        int4 dv = __ldcs(reinterpret_cast<const int4*>(dst) + i);
        s[0] = sv.x; s[1] = sv.y; s[2] = sv.z; s[3] = sv.w;
        d[0] = dv.x; d[1] = dv.y; d[2] = dv.z; d[3] = dv.w;
    } else {
        const long long* src = (const long long*)ei;
        const long long* dst = src + NUM_EDGES;
        longlong2 s0 = __ldcs(reinterpret_cast<const longlong2*>(src) + 2 * i);
        longlong2 s1 = __ldcs(reinterpret_cast<const longlong2*>(src) + 2 * i + 1);
        longlong2 d0 = __ldcs(reinterpret_cast<const longlong2*>(dst) + 2 * i);
        longlong2 d1 = __ldcs(reinterpret_cast<const longlong2*>(dst) + 2 * i + 1);
        s[0] = (unsigned)s0.x; s[1] = (unsigned)s0.y; s[2] = (unsigned)s1.x; s[3] = (unsigned)s1.y;
        d[0] = (unsigned)d0.x; d[1] = (unsigned)d0.y; d[2] = (unsigned)d1.x; d[3] = (unsigned)d1.y;
    }
    #pragma unroll
    for (int e = 0; e < 4; e++) {
        if (s[e] < NUM_NODES && d[e] < NUM_NODES) {
            int p = atomicAdd(&g_cursor[d[e]], 1);
            g_sorted[p] = (int)s[e];
        }
    }
}

// ---------------------------------------------------------------------------
// gather + fused transform. One thread per node, accumulation in registers,
// NO atomics. PHASE 0: feat=g_x8, write padded h into g_h8.
// PHASE 1: feat=g_h8, argmax (first-max wins) -> one-hot into out.
// ---------------------------------------------------------------------------
template <int PHASE>
__global__ void gather_kernel(const float* __restrict__ Wrel,
                              const float* __restrict__ Wroot,
                              const float* __restrict__ b,
                              float* __restrict__ out) {
    __shared__ float swr[36], swo[36], sb[6];
    int t = threadIdx.x;
    if (t < 36)        swr[t]      = Wrel[t];
    else if (t < 72)   swo[t - 36] = Wroot[t - 36];
    else if (t < 78)   sb[t - 72]  = b[t - 72];
    __syncthreads();

    int i = blockIdx.x * blockDim.x + t;
    if (i >= NUM_NODES) return;

    const float* feat = PHASE ? g_h8 : g_x8;
    int start = g_rowst[i];
    int deg   = g_cnt[i];

    float ag[6] = {0.f, 0.f, 0.f, 0.f, 0.f, 0.f};
    int j = 0;
    for (; j + 1 < deg; j += 2) {                       // 2-way MLP
        int s0 = g_sorted[start + j];
        int s1 = g_sorted[start + j + 1];
        const float* r0 = feat + (size_t)s0 * FP;
        const float* r1 = feat + (size_t)s1 * FP;
        float4 a0 = *reinterpret_cast<const float4*>(r0);
        float2 b0 = *reinterpret_cast<const float2*>(r0 + 4);
        float4 a1 = *reinterpret_cast<const float4*>(r1);
        float2 b1 = *reinterpret_cast<const float2*>(r1 + 4);
        ag[0] += a0.x + a1.x;  ag[1] += a0.y + a1.y;
        ag[2] += a0.z + a1.z;  ag[3] += a0.w + a1.w;
        ag[4] += b0.x + b1.x;  ag[5] += b0.y + b1.y;
    }
    if (j < deg) {
        int s0 = g_sorted[start + j];
        const float* r0 = feat + (size_t)s0 * FP;
        float4 a0 = *reinterpret_cast<const float4*>(r0);
        float2 b0 = *reinterpret_cast<const float2*>(r0 + 4);
        ag[0] += a0.x; ag[1] += a0.y; ag[2] += a0.z;
        ag[3] += a0.w; ag[4] += b0.x; ag[5] += b0.y;
    }

    const float* xr = feat + (size_t)i * FP;            // root input = same table
    float4 x0 = *reinterpret_cast<const float4*>(xr);
    float2 x1 = *reinterpret_cast<const float2*>(xr + 4);
    float xv[6] = {x0.x, x0.y, x0.z, x0.w, x1.x, x1.y};

    float h[6];
    #pragma unroll
    for (int k = 0; k < 6; k++) {
        float acc = sb[k];
        #pragma unroll
        for (int m = 0; m < 6; m++) {
            acc = fmaf(ag[m], swr[k * 6 + m], acc);
            acc = fmaf(xv[m], swo[k * 6 + m], acc);
        }
        h[k] = acc;
    }

    if (PHASE == 0) {
        float4* ph = reinterpret_cast<float4*>(g_h8 + (size_t)i * FP);
        ph[0] = make_float4(h[0], h[1], h[2], h[3]);
        ph[1] = make_float4(h[4], h[5], 0.f, 0.f);
    } else {
        int best = 0; float bv = h[0];
        #pragma unroll
        for (int k = 1; k < 6; k++)
            if (h[k] > bv) { bv = h[k]; best = k; }     // first-max = jnp.argmax
        float* po = out + (size_t)i * F;
        #pragma unroll
        for (int k = 0; k < 6; k++)
            po[k] = (k == best) ? 1.f : 0.f;
    }
}

extern "C" void kernel_launch(void* const* d_in, const int* in_sizes, int n_in,
                              void* d_out, int out_size) {
    const float* x      = (const float*)d_in[0];
    const void*  ei     = d_in[1];
    const float* Wrel1  = (const float*)d_in[2];
    const float* Wroot1 = (const float*)d_in[3];
    const float* b1     = (const float*)d_in[4];
    const float* Wrel2  = (const float*)d_in[5];
    const float* Wroot2 = (const float*)d_in[6];
    const float* b2     = (const float*)d_in[7];
    float*       out    = (float*)d_out;

    const int BLK = 256;
    const int node_grid = (NUM_NODES + BLK - 1) / BLK;
    const int quad_grid = (NUM_EDGES / 4 + BLK - 1) / BLK;

    detect_kernel<<<1, 256>>>((const long long*)ei);
    prep_kernel<<<node_grid, BLK>>>(x);
    // Build CSR grouping (once; reused by both layers)
    hist_kernel<<<quad_grid, BLK>>>(ei);
    scan1_kernel<<<NBLK, SCAN_BLK>>>();
    scan2_kernel<<<1, SCAN_BLK>>>();
    scan3_kernel<<<NBLK, SCAN_BLK>>>();
    reorder_kernel<<<quad_grid, BLK>>>(ei);
    // Two fused gather+transform layers (no atomics)
    gather_kernel<0><<<node_grid, BLK>>>(Wrel1, Wroot1, b1, nullptr);
    gather_kernel<1><<<node_grid, BLK>>>(Wrel2, Wroot2, b2, out);
}